// round 4
// baseline (speedup 1.0000x reference)
#include <cuda_runtime.h>
#include <cuda_bf16.h>

#define NNODES 8192
#define NEDGES 262144
#define NFEAT  128
#define NREP   4

// ---------------- device scratch (no allocation allowed) ----------------
__device__ __align__(16) float g_support[NNODES * NFEAT];   // x @ W  (4 MB)
__device__ __align__(16) float g_deg4[NNODES * NREP];       // replicated degree
__device__ __align__(16) float g_dinv[NNODES];
__device__ __align__(16) int   g_cnt4[NNODES * NREP];       // replicated counts
__device__ __align__(16) int   g_row_ptr[NNODES + 1];       // CSR offsets
__device__ __align__(16) int   g_fill4[NNODES * NREP];      // replicated cursors
__device__ __align__(16) int2  g_epack[NEDGES];             // packed {col, w}

// ---------------- K1: init (32768 replicated slots) ----------------
__global__ void k_init() {
    int i = blockIdx.x * blockDim.x + threadIdx.x;
    if (i < NNODES * NREP) {
        g_cnt4[i] = 0;
        g_deg4[i] = ((i & 3) == 0) ? 1.0f : 0.0f;   // self-loop in rep 0
    }
}

// ---------------- K2: edge pass 1 (degree + histogram, 4 edges/thread) -----
__global__ void k_edge_count(const int* __restrict__ rows,
                             const float* __restrict__ ew) {
    int t = blockIdx.x * blockDim.x + threadIdx.x;     // NEDGES/4 threads
    int e0 = t * 4;
    int4   r4 = *(const int4*)&rows[e0];
    float4 w4 = *(const float4*)&ew[e0];
    // rep = edge & 3  (must match k_edge_scatter)
    atomicAdd(&g_cnt4[r4.x * 4 + 0], 1);
    atomicAdd(&g_cnt4[r4.y * 4 + 1], 1);
    atomicAdd(&g_cnt4[r4.z * 4 + 2], 1);
    atomicAdd(&g_cnt4[r4.w * 4 + 3], 1);
    atomicAdd(&g_deg4[r4.x * 4 + 0], w4.x);
    atomicAdd(&g_deg4[r4.y * 4 + 1], w4.y);
    atomicAdd(&g_deg4[r4.z * 4 + 2], w4.z);
    atomicAdd(&g_deg4[r4.w * 4 + 3], w4.w);
}

// ---------------- K3: shfl scan over 32768 counts + fused deg/dinv ---------
// 1024 threads, 32 entries (= 8 rows x 4 reps) per thread, 2 barriers.
__global__ __launch_bounds__(1024) void k_scan() {
    __shared__ int warp_tot[32];
    int t    = threadIdx.x;
    int lane = t & 31;
    int wid  = t >> 5;
    int base = t * 32;            // entry index
    int row0 = t * 8;             // first row this thread owns

    int c[32];
#pragma unroll
    for (int q = 0; q < 8; q++) {
        int4 v = *(const int4*)&g_cnt4[base + q * 4];
        c[q * 4 + 0] = v.x; c[q * 4 + 1] = v.y;
        c[q * 4 + 2] = v.z; c[q * 4 + 3] = v.w;
    }
    int run = 0;
#pragma unroll
    for (int j = 0; j < 32; j++) run += c[j];

    // inclusive warp scan of per-thread totals
    int v = run;
#pragma unroll
    for (int off = 1; off < 32; off <<= 1) {
        int u = __shfl_up_sync(0xffffffffu, v, off);
        if (lane >= off) v += u;
    }
    if (lane == 31) warp_tot[wid] = v;
    __syncthreads();
    if (wid == 0) {
        int w = warp_tot[lane];
#pragma unroll
        for (int off = 1; off < 32; off <<= 1) {
            int u = __shfl_up_sync(0xffffffffu, w, off);
            if (lane >= off) w += u;
        }
        warp_tot[lane] = w;
    }
    __syncthreads();

    int pos = v - run + (wid ? warp_tot[wid - 1] : 0);   // exclusive base
#pragma unroll
    for (int j = 0; j < 32; j++) {
        g_fill4[base + j] = pos;
        if ((j & 3) == 0) g_row_ptr[row0 + (j >> 2)] = pos;
        pos += c[j];
    }
    if (t == 1023) g_row_ptr[NNODES] = warp_tot[31];

    // fused deg reduction + dinv for this thread's 8 rows
    float dv[8];
#pragma unroll
    for (int q = 0; q < 8; q++) {
        float4 d = *(const float4*)&g_deg4[(row0 + q) * 4];
        dv[q] = rsqrtf(d.x + d.y + d.z + d.w + 1e-10f);
    }
    *(float4*)&g_dinv[row0]     = make_float4(dv[0], dv[1], dv[2], dv[3]);
    *(float4*)&g_dinv[row0 + 4] = make_float4(dv[4], dv[5], dv[6], dv[7]);
}

// ---------------- K4: edge pass 2 (scatter packed records, 4 edges/thread) --
__global__ void k_edge_scatter(const int* __restrict__ rows,
                               const int* __restrict__ cols,
                               const float* __restrict__ ew) {
    int t = blockIdx.x * blockDim.x + threadIdx.x;
    int e0 = t * 4;
    int4   r4 = *(const int4*)&rows[e0];
    int4   c4 = *(const int4*)&cols[e0];
    float4 w4 = *(const float4*)&ew[e0];
    int p0 = atomicAdd(&g_fill4[r4.x * 4 + 0], 1);
    int p1 = atomicAdd(&g_fill4[r4.y * 4 + 1], 1);
    int p2 = atomicAdd(&g_fill4[r4.z * 4 + 2], 1);
    int p3 = atomicAdd(&g_fill4[r4.w * 4 + 3], 1);
    g_epack[p0] = make_int2(c4.x, __float_as_int(w4.x));
    g_epack[p1] = make_int2(c4.y, __float_as_int(w4.y));
    g_epack[p2] = make_int2(c4.z, __float_as_int(w4.z));
    g_epack[p3] = make_int2(c4.w, __float_as_int(w4.w));
}

// ---------------- packed f32x2 helpers ----------------
__device__ __forceinline__ unsigned long long pack2(float lo, float hi) {
    unsigned long long r;
    asm("mov.b64 %0, {%1, %2};" : "=l"(r) : "f"(lo), "f"(hi));
    return r;
}
__device__ __forceinline__ void fma2(unsigned long long& d,
                                     unsigned long long a,
                                     unsigned long long b) {
    asm("fma.rn.f32x2 %0, %1, %2, %0;" : "+l"(d) : "l"(a), "l"(b));
}
__device__ __forceinline__ float2 unpack2(unsigned long long p) {
    float lo, hi;
    asm("mov.b64 {%0, %1}, %2;" : "=f"(lo), "=f"(hi) : "l"(p));
    return make_float2(lo, hi);
}

// ---------------- K5: support = x @ W  (8192x128x128 fp32, f32x2 FMA) -------
__global__ __launch_bounds__(256) void k_gemm(const float* __restrict__ x,
                                              const float* __restrict__ w) {
    __shared__ __align__(16) float s_x[32][32];
    __shared__ __align__(16) float s_w[32][128];
    int tid = threadIdx.x;
    int row_base = blockIdx.x * 32;
    int c0 = (tid & 31) * 4;
    int r0 = (tid >> 5) * 4;

    unsigned long long acc2[4][2];
#pragma unroll
    for (int i = 0; i < 4; i++) { acc2[i][0] = 0ull; acc2[i][1] = 0ull; }

    for (int kk = 0; kk < 128; kk += 32) {
#pragma unroll
        for (int q = 0; q < 4; q++) {
            int e = tid + 256 * q;
            int r = e >> 5, kl = e & 31;
            s_x[r][kl] = x[(row_base + r) * 128 + kk + kl];
        }
#pragma unroll
        for (int q = 0; q < 4; q++) {
            int p = tid + 256 * q;
            int kr = p >> 5, cc = (p & 31) * 4;
            *(float4*)&s_w[kr][cc] = *(const float4*)&w[(kk + kr) * 128 + cc];
        }
        __syncthreads();
#pragma unroll
        for (int k = 0; k < 32; k++) {
            float4 bv = *(float4*)&s_w[k][c0];
            unsigned long long b01 = pack2(bv.x, bv.y);
            unsigned long long b23 = pack2(bv.z, bv.w);
#pragma unroll
            for (int i = 0; i < 4; i++) {
                float av = s_x[r0 + i][k];
                unsigned long long aa = pack2(av, av);
                fma2(acc2[i][0], aa, b01);
                fma2(acc2[i][1], aa, b23);
            }
        }
        __syncthreads();
    }
#pragma unroll
    for (int i = 0; i < 4; i++) {
        float2 lo = unpack2(acc2[i][0]);
        float2 hi = unpack2(acc2[i][1]);
        *(float4*)&g_support[(row_base + r0 + i) * 128 + c0] =
            make_float4(lo.x, lo.y, hi.x, hi.y);
    }
}

// ---------------- K6: SpMM gather + normalize + bias ----------------
__global__ __launch_bounds__(256) void k_spmm(const float* __restrict__ bias,
                                              float* __restrict__ out) {
    int warp = (blockIdx.x * blockDim.x + threadIdx.x) >> 5;
    int lane = threadIdx.x & 31;
    if (warp >= NNODES) return;
    int row = warp;
    int s = g_row_ptr[row];
    int e = g_row_ptr[row + 1];
    float di = g_dinv[row];

    float ax = 0.f, ay = 0.f, az = 0.f, aw = 0.f;
    int foff = lane * 4;

    int i = s;
    for (; i + 3 < e; i += 4) {
        int2 e0 = g_epack[i];
        int2 e1 = g_epack[i + 1];
        int2 e2 = g_epack[i + 2];
        int2 e3 = g_epack[i + 3];
        float v0 = __int_as_float(e0.y) * g_dinv[e0.x];
        float v1 = __int_as_float(e1.y) * g_dinv[e1.x];
        float v2 = __int_as_float(e2.y) * g_dinv[e2.x];
        float v3 = __int_as_float(e3.y) * g_dinv[e3.x];
        float4 s0 = *(const float4*)&g_support[e0.x * 128 + foff];
        float4 s1 = *(const float4*)&g_support[e1.x * 128 + foff];
        float4 s2 = *(const float4*)&g_support[e2.x * 128 + foff];
        float4 s3 = *(const float4*)&g_support[e3.x * 128 + foff];
        ax += v0 * s0.x + v1 * s1.x + v2 * s2.x + v3 * s3.x;
        ay += v0 * s0.y + v1 * s1.y + v2 * s2.y + v3 * s3.y;
        az += v0 * s0.z + v1 * s1.z + v2 * s2.z + v3 * s3.z;
        aw += v0 * s0.w + v1 * s1.w + v2 * s2.w + v3 * s3.w;
    }
    for (; i < e; i++) {
        int2 e0 = g_epack[i];
        float v0 = __int_as_float(e0.y) * g_dinv[e0.x];
        float4 s0 = *(const float4*)&g_support[e0.x * 128 + foff];
        ax += v0 * s0.x; ay += v0 * s0.y; az += v0 * s0.z; aw += v0 * s0.w;
    }
    // self-loop: dinv[row]^2 * support[row]
    {
        float4 sv = *(const float4*)&g_support[row * 128 + foff];
        ax += di * sv.x; ay += di * sv.y; az += di * sv.z; aw += di * sv.w;
    }
    float4 b = *(const float4*)&bias[foff];
    float4 o;
    o.x = di * ax + b.x;
    o.y = di * ay + b.y;
    o.z = di * az + b.z;
    o.w = di * aw + b.w;
    *(float4*)&out[row * 128 + foff] = o;
}

// ---------------- launch ----------------
extern "C" void kernel_launch(void* const* d_in, const int* in_sizes, int n_in,
                              void* d_out, int out_size) {
    const float* x    = (const float*)d_in[0];
    const int*   adj  = (const int*)d_in[1];     // int32 [2, E]
    const float* ew   = (const float*)d_in[2];
    const float* wgt  = (const float*)d_in[3];
    const float* bias = (const float*)d_in[4];
    float* out = (float*)d_out;

    const int* rows = adj;
    const int* cols = adj + NEDGES;

    k_init<<<(NNODES * NREP + 255) / 256, 256>>>();
    k_edge_count<<<(NEDGES / 4 + 255) / 256, 256>>>(rows, ew);
    k_scan<<<1, 1024>>>();
    k_edge_scatter<<<(NEDGES / 4 + 255) / 256, 256>>>(rows, cols, ew);
    k_gemm<<<NNODES / 32, 256>>>(x, wgt);
    k_spmm<<<NNODES / 8, 256>>>(bias, out);
}

// round 5
// speedup vs baseline: 1.0646x; 1.0646x over previous
#include <cuda_runtime.h>
#include <cuda_bf16.h>

#define NNODES 8192
#define NEDGES 262144
#define NFEAT  128
#define NREP   4

// ---------------- device scratch (no allocation allowed) ----------------
__device__ __align__(16) float g_support[NNODES * NFEAT];   // x @ W  (4 MB)
__device__ __align__(16) float g_deg4[NNODES * NREP];       // replicated degree
__device__ __align__(16) float g_dinv[NNODES];
__device__ __align__(16) int   g_cnt4[NNODES * NREP];       // replicated counts
__device__ __align__(16) int   g_row_ptr[NNODES + 1];       // CSR offsets
__device__ __align__(16) int   g_fill4[NNODES * NREP];      // replicated cursors
__device__ __align__(16) int2  g_epack[NEDGES];             // packed {col, w}

// ---------------- K1: edge pass 1 (degree + histogram, thread/edge) --------
__global__ void k_edge_count(const int* __restrict__ rows,
                             const float* __restrict__ ew) {
    int e = blockIdx.x * blockDim.x + threadIdx.x;
    int r = rows[e];
    int rep = e & 3;
    atomicAdd(&g_cnt4[r * 4 + rep], 1);
    atomicAdd(&g_deg4[r * 4 + rep], ew[e]);
}

// ---------------- K2: shfl scan over 32768 counts + fused deg/dinv ---------
// 1024 threads, 32 entries (= 8 rows x 4 reps) per thread, 2 barriers.
__global__ __launch_bounds__(1024) void k_scan() {
    __shared__ int warp_tot[32];
    int t    = threadIdx.x;
    int lane = t & 31;
    int wid  = t >> 5;
    int base = t * 32;            // entry index
    int row0 = t * 8;             // first row this thread owns

    int c[32];
#pragma unroll
    for (int q = 0; q < 8; q++) {
        int4 v = *(const int4*)&g_cnt4[base + q * 4];
        c[q * 4 + 0] = v.x; c[q * 4 + 1] = v.y;
        c[q * 4 + 2] = v.z; c[q * 4 + 3] = v.w;
    }
    int run = 0;
#pragma unroll
    for (int j = 0; j < 32; j++) run += c[j];

    // inclusive warp scan of per-thread totals
    int v = run;
#pragma unroll
    for (int off = 1; off < 32; off <<= 1) {
        int u = __shfl_up_sync(0xffffffffu, v, off);
        if (lane >= off) v += u;
    }
    if (lane == 31) warp_tot[wid] = v;
    __syncthreads();
    if (wid == 0) {
        int w = warp_tot[lane];
#pragma unroll
        for (int off = 1; off < 32; off <<= 1) {
            int u = __shfl_up_sync(0xffffffffu, w, off);
            if (lane >= off) w += u;
        }
        warp_tot[lane] = w;
    }
    __syncthreads();

    int pos = v - run + (wid ? warp_tot[wid - 1] : 0);   // exclusive base
#pragma unroll
    for (int j = 0; j < 32; j++) {
        g_fill4[base + j] = pos;
        if ((j & 3) == 0) g_row_ptr[row0 + (j >> 2)] = pos;
        pos += c[j];
    }
    if (t == 1023) g_row_ptr[NNODES] = warp_tot[31];

    // fused deg reduction (+1 self-loop) + dinv for this thread's 8 rows
    float dv[8];
#pragma unroll
    for (int q = 0; q < 8; q++) {
        float4 d = *(const float4*)&g_deg4[(row0 + q) * 4];
        dv[q] = rsqrtf(1.0f + d.x + d.y + d.z + d.w + 1e-10f);
    }
    *(float4*)&g_dinv[row0]     = make_float4(dv[0], dv[1], dv[2], dv[3]);
    *(float4*)&g_dinv[row0 + 4] = make_float4(dv[4], dv[5], dv[6], dv[7]);
}

// ---------------- K3: edge pass 2 (scatter packed records, thread/edge) ----
__global__ void k_edge_scatter(const int* __restrict__ rows,
                               const int* __restrict__ cols,
                               const float* __restrict__ ew) {
    int e = blockIdx.x * blockDim.x + threadIdx.x;
    int r = rows[e];
    int rep = e & 3;
    int pos = atomicAdd(&g_fill4[r * 4 + rep], 1);
    g_epack[pos] = make_int2(cols[e], __float_as_int(ew[e]));
}

// ---------------- packed f32x2 helpers ----------------
__device__ __forceinline__ unsigned long long pack2(float lo, float hi) {
    unsigned long long r;
    asm("mov.b64 %0, {%1, %2};" : "=l"(r) : "f"(lo), "f"(hi));
    return r;
}
__device__ __forceinline__ void fma2(unsigned long long& d,
                                     unsigned long long a,
                                     unsigned long long b) {
    asm("fma.rn.f32x2 %0, %1, %2, %0;" : "+l"(d) : "l"(a), "l"(b));
}
__device__ __forceinline__ float2 unpack2(unsigned long long p) {
    float lo, hi;
    asm("mov.b64 {%0, %1}, %2;" : "=f"(lo), "=f"(hi) : "l"(p));
    return make_float2(lo, hi);
}

// ---------------- K4: support = x @ W  (8192x128x128 fp32, f32x2 FMA) -------
__global__ __launch_bounds__(256) void k_gemm(const float* __restrict__ x,
                                              const float* __restrict__ w) {
    __shared__ __align__(16) float s_x[32][32];
    __shared__ __align__(16) float s_w[32][128];
    int tid = threadIdx.x;
    int row_base = blockIdx.x * 32;
    int c0 = (tid & 31) * 4;
    int r0 = (tid >> 5) * 4;

    unsigned long long acc2[4][2];
#pragma unroll
    for (int i = 0; i < 4; i++) { acc2[i][0] = 0ull; acc2[i][1] = 0ull; }

    for (int kk = 0; kk < 128; kk += 32) {
#pragma unroll
        for (int q = 0; q < 4; q++) {
            int e = tid + 256 * q;
            int r = e >> 5, kl = e & 31;
            s_x[r][kl] = x[(row_base + r) * 128 + kk + kl];
        }
#pragma unroll
        for (int q = 0; q < 4; q++) {
            int p = tid + 256 * q;
            int kr = p >> 5, cc = (p & 31) * 4;
            *(float4*)&s_w[kr][cc] = *(const float4*)&w[(kk + kr) * 128 + cc];
        }
        __syncthreads();
#pragma unroll
        for (int k = 0; k < 32; k++) {
            float4 bv = *(float4*)&s_w[k][c0];
            unsigned long long b01 = pack2(bv.x, bv.y);
            unsigned long long b23 = pack2(bv.z, bv.w);
#pragma unroll
            for (int i = 0; i < 4; i++) {
                float av = s_x[r0 + i][k];
                unsigned long long aa = pack2(av, av);
                fma2(acc2[i][0], aa, b01);
                fma2(acc2[i][1], aa, b23);
            }
        }
        __syncthreads();
    }
#pragma unroll
    for (int i = 0; i < 4; i++) {
        float2 lo = unpack2(acc2[i][0]);
        float2 hi = unpack2(acc2[i][1]);
        *(float4*)&g_support[(row_base + r0 + i) * 128 + c0] =
            make_float4(lo.x, lo.y, hi.x, hi.y);
    }
}

// ---------------- K5: SpMM gather + normalize + bias ----------------
__global__ __launch_bounds__(256) void k_spmm(const float* __restrict__ bias,
                                              float* __restrict__ out) {
    int warp = (blockIdx.x * blockDim.x + threadIdx.x) >> 5;
    int lane = threadIdx.x & 31;
    if (warp >= NNODES) return;
    int row = warp;
    int s = g_row_ptr[row];
    int e = g_row_ptr[row + 1];
    float di = g_dinv[row];

    float ax = 0.f, ay = 0.f, az = 0.f, aw = 0.f;
    int foff = lane * 4;

    int i = s;
    for (; i + 3 < e; i += 4) {
        int2 e0 = g_epack[i];
        int2 e1 = g_epack[i + 1];
        int2 e2 = g_epack[i + 2];
        int2 e3 = g_epack[i + 3];
        float v0 = __int_as_float(e0.y) * g_dinv[e0.x];
        float v1 = __int_as_float(e1.y) * g_dinv[e1.x];
        float v2 = __int_as_float(e2.y) * g_dinv[e2.x];
        float v3 = __int_as_float(e3.y) * g_dinv[e3.x];
        float4 s0 = *(const float4*)&g_support[e0.x * 128 + foff];
        float4 s1 = *(const float4*)&g_support[e1.x * 128 + foff];
        float4 s2 = *(const float4*)&g_support[e2.x * 128 + foff];
        float4 s3 = *(const float4*)&g_support[e3.x * 128 + foff];
        ax += v0 * s0.x + v1 * s1.x + v2 * s2.x + v3 * s3.x;
        ay += v0 * s0.y + v1 * s1.y + v2 * s2.y + v3 * s3.y;
        az += v0 * s0.z + v1 * s1.z + v2 * s2.z + v3 * s3.z;
        aw += v0 * s0.w + v1 * s1.w + v2 * s2.w + v3 * s3.w;
    }
    for (; i < e; i++) {
        int2 e0 = g_epack[i];
        float v0 = __int_as_float(e0.y) * g_dinv[e0.x];
        float4 s0 = *(const float4*)&g_support[e0.x * 128 + foff];
        ax += v0 * s0.x; ay += v0 * s0.y; az += v0 * s0.z; aw += v0 * s0.w;
    }
    // self-loop: dinv[row]^2 * support[row]
    {
        float4 sv = *(const float4*)&g_support[row * 128 + foff];
        ax += di * sv.x; ay += di * sv.y; az += di * sv.z; aw += di * sv.w;
    }
    float4 b = *(const float4*)&bias[foff];
    float4 o;
    o.x = di * ax + b.x;
    o.y = di * ay + b.y;
    o.z = di * az + b.z;
    o.w = di * aw + b.w;
    *(float4*)&out[row * 128 + foff] = o;
}

// ---------------- launch ----------------
extern "C" void kernel_launch(void* const* d_in, const int* in_sizes, int n_in,
                              void* d_out, int out_size) {
    const float* x    = (const float*)d_in[0];
    const int*   adj  = (const int*)d_in[1];     // int32 [2, E]
    const float* ew   = (const float*)d_in[2];
    const float* wgt  = (const float*)d_in[3];
    const float* bias = (const float*)d_in[4];
    float* out = (float*)d_out;

    const int* rows = adj;
    const int* cols = adj + NEDGES;

    // one-time side resources (host-side only; no device allocation)
    static cudaStream_t s2 = nullptr;
    static cudaEvent_t evA = nullptr, evB = nullptr;
    if (s2 == nullptr) {
        cudaStreamCreateWithFlags(&s2, cudaStreamNonBlocking);
        cudaEventCreateWithFlags(&evA, cudaEventDisableTiming);
        cudaEventCreateWithFlags(&evB, cudaEventDisableTiming);
    }

    // fork: GEMM (depends only on x, W) runs concurrently with the CSR build
    cudaEventRecord(evA, 0);
    cudaStreamWaitEvent(s2, evA, 0);
    k_gemm<<<NNODES / 32, 256, 0, s2>>>(x, wgt);
    cudaEventRecord(evB, s2);

    // CSR build on the main (capture) stream
    void* cnt_ptr = nullptr; cudaGetSymbolAddress(&cnt_ptr, g_cnt4);
    void* deg_ptr = nullptr; cudaGetSymbolAddress(&deg_ptr, g_deg4);
    cudaMemsetAsync(cnt_ptr, 0, NNODES * NREP * sizeof(int), 0);
    cudaMemsetAsync(deg_ptr, 0, NNODES * NREP * sizeof(float), 0);
    k_edge_count<<<NEDGES / 256, 256>>>(rows, ew);
    k_scan<<<1, 1024>>>();
    k_edge_scatter<<<NEDGES / 256, 256>>>(rows, cols, ew);

    // join, then SpMM
    cudaStreamWaitEvent(0, evB, 0);
    k_spmm<<<NNODES / 8, 256>>>(bias, out);
}

// round 6
// speedup vs baseline: 1.4099x; 1.3243x over previous
#include <cuda_runtime.h>
#include <cuda_bf16.h>

#define NNODES 8192
#define NEDGES 262144
#define NFEAT  128
#define NREP   4
#define CAP    48        // max edges per (row, rep) sub-bucket

// ---------------- device scratch (no allocation allowed) ----------------
__device__ __align__(16) float g_support[NNODES * NFEAT];        // x @ W (4 MB)
__device__ __align__(16) float g_deg4[NNODES * NREP];            // replicated degree
__device__ __align__(16) float g_dinv[NNODES];
__device__ __align__(16) int   g_cnt4[NNODES * NREP];            // bucket cursors
__device__ __align__(16) int2  g_bucket[NNODES * NREP * CAP];    // {col, w} (12.6 MB)

// ---------------- K1: single-pass bucketed scatter + degree ----------------
__global__ void k_scatter(const int* __restrict__ rows,
                          const int* __restrict__ cols,
                          const float* __restrict__ ew) {
    int e = blockIdx.x * blockDim.x + threadIdx.x;
    int r = rows[e];
    int rep = e & 3;
    float w = ew[e];
    int slot = r * 4 + rep;
    int pos = atomicAdd(&g_cnt4[slot], 1);
    g_bucket[slot * CAP + pos] = make_int2(cols[e], __float_as_int(w));
    atomicAdd(&g_deg4[slot], w);
}

// ---------------- K2: dinv = rsqrt(1 + deg + eps) ----------------
__global__ void k_dinv() {
    int i = blockIdx.x * blockDim.x + threadIdx.x;
    if (i < NNODES) {
        float4 d = *(const float4*)&g_deg4[i * 4];
        g_dinv[i] = rsqrtf(1.0f + d.x + d.y + d.z + d.w + 1e-10f);
    }
}

// ---------------- packed f32x2 helpers ----------------
__device__ __forceinline__ unsigned long long pack2(float lo, float hi) {
    unsigned long long r;
    asm("mov.b64 %0, {%1, %2};" : "=l"(r) : "f"(lo), "f"(hi));
    return r;
}
__device__ __forceinline__ void fma2(unsigned long long& d,
                                     unsigned long long a,
                                     unsigned long long b) {
    asm("fma.rn.f32x2 %0, %1, %2, %0;" : "+l"(d) : "l"(a), "l"(b));
}
__device__ __forceinline__ float2 unpack2(unsigned long long p) {
    float lo, hi;
    asm("mov.b64 {%0, %1}, %2;" : "=f"(lo), "=f"(hi) : "l"(p));
    return make_float2(lo, hi);
}

// ---------------- K3: support = x @ W  (8192x128x128 fp32, f32x2 FMA) -------
__global__ __launch_bounds__(256) void k_gemm(const float* __restrict__ x,
                                              const float* __restrict__ w) {
    __shared__ __align__(16) float s_x[32][32];
    __shared__ __align__(16) float s_w[32][128];
    int tid = threadIdx.x;
    int row_base = blockIdx.x * 32;
    int c0 = (tid & 31) * 4;
    int r0 = (tid >> 5) * 4;

    unsigned long long acc2[4][2];
#pragma unroll
    for (int i = 0; i < 4; i++) { acc2[i][0] = 0ull; acc2[i][1] = 0ull; }

    for (int kk = 0; kk < 128; kk += 32) {
#pragma unroll
        for (int q = 0; q < 4; q++) {
            int e = tid + 256 * q;
            int r = e >> 5, kl = e & 31;
            s_x[r][kl] = x[(row_base + r) * 128 + kk + kl];
        }
#pragma unroll
        for (int q = 0; q < 4; q++) {
            int p = tid + 256 * q;
            int kr = p >> 5, cc = (p & 31) * 4;
            *(float4*)&s_w[kr][cc] = *(const float4*)&w[(kk + kr) * 128 + cc];
        }
        __syncthreads();
#pragma unroll
        for (int k = 0; k < 32; k++) {
            float4 bv = *(float4*)&s_w[k][c0];
            unsigned long long b01 = pack2(bv.x, bv.y);
            unsigned long long b23 = pack2(bv.z, bv.w);
#pragma unroll
            for (int i = 0; i < 4; i++) {
                float av = s_x[r0 + i][k];
                unsigned long long aa = pack2(av, av);
                fma2(acc2[i][0], aa, b01);
                fma2(acc2[i][1], aa, b23);
            }
        }
        __syncthreads();
    }
#pragma unroll
    for (int i = 0; i < 4; i++) {
        float2 lo = unpack2(acc2[i][0]);
        float2 hi = unpack2(acc2[i][1]);
        *(float4*)&g_support[(row_base + r0 + i) * 128 + c0] =
            make_float4(lo.x, lo.y, hi.x, hi.y);
    }
}

// ---------------- K4: SpMM over buckets + normalize + bias ----------------
// One warp per output row; each lane owns 4 features (float4).
__global__ __launch_bounds__(256) void k_spmm(const float* __restrict__ bias,
                                              float* __restrict__ out) {
    int warp = (blockIdx.x * blockDim.x + threadIdx.x) >> 5;
    int lane = threadIdx.x & 31;
    if (warp >= NNODES) return;
    int row = warp;
    float di = g_dinv[row];
    int4 cnt = *(const int4*)&g_cnt4[row * 4];
    int n[4] = {cnt.x, cnt.y, cnt.z, cnt.w};

    float ax = 0.f, ay = 0.f, az = 0.f, aw = 0.f;
    int foff = lane * 4;

#pragma unroll
    for (int rep = 0; rep < 4; rep++) {
        const int2* bk = &g_bucket[(row * 4 + rep) * CAP];
        int e = n[rep];
        int i = 0;
        for (; i + 3 < e; i += 4) {
            int2 e0 = bk[i];
            int2 e1 = bk[i + 1];
            int2 e2 = bk[i + 2];
            int2 e3 = bk[i + 3];
            float v0 = __int_as_float(e0.y) * g_dinv[e0.x];
            float v1 = __int_as_float(e1.y) * g_dinv[e1.x];
            float v2 = __int_as_float(e2.y) * g_dinv[e2.x];
            float v3 = __int_as_float(e3.y) * g_dinv[e3.x];
            float4 s0 = *(const float4*)&g_support[e0.x * 128 + foff];
            float4 s1 = *(const float4*)&g_support[e1.x * 128 + foff];
            float4 s2 = *(const float4*)&g_support[e2.x * 128 + foff];
            float4 s3 = *(const float4*)&g_support[e3.x * 128 + foff];
            ax += v0 * s0.x + v1 * s1.x + v2 * s2.x + v3 * s3.x;
            ay += v0 * s0.y + v1 * s1.y + v2 * s2.y + v3 * s3.y;
            az += v0 * s0.z + v1 * s1.z + v2 * s2.z + v3 * s3.z;
            aw += v0 * s0.w + v1 * s1.w + v2 * s2.w + v3 * s3.w;
        }
        for (; i < e; i++) {
            int2 e0 = bk[i];
            float v0 = __int_as_float(e0.y) * g_dinv[e0.x];
            float4 s0 = *(const float4*)&g_support[e0.x * 128 + foff];
            ax += v0 * s0.x; ay += v0 * s0.y; az += v0 * s0.z; aw += v0 * s0.w;
        }
    }
    // self-loop: dinv[row]^2 * support[row]
    {
        float4 sv = *(const float4*)&g_support[row * 128 + foff];
        ax += di * sv.x; ay += di * sv.y; az += di * sv.z; aw += di * sv.w;
    }
    float4 b = *(const float4*)&bias[foff];
    float4 o;
    o.x = di * ax + b.x;
    o.y = di * ay + b.y;
    o.z = di * az + b.z;
    o.w = di * aw + b.w;
    *(float4*)&out[row * 128 + foff] = o;
}

// ---------------- launch ----------------
extern "C" void kernel_launch(void* const* d_in, const int* in_sizes, int n_in,
                              void* d_out, int out_size) {
    const float* x    = (const float*)d_in[0];
    const int*   adj  = (const int*)d_in[1];     // int32 [2, E]
    const float* ew   = (const float*)d_in[2];
    const float* wgt  = (const float*)d_in[3];
    const float* bias = (const float*)d_in[4];
    float* out = (float*)d_out;

    const int* rows = adj;
    const int* cols = adj + NEDGES;

    // one-time side resources (host-side only; no device allocation)
    static cudaStream_t s2 = nullptr;
    static cudaEvent_t evA = nullptr, evB = nullptr;
    if (s2 == nullptr) {
        cudaStreamCreateWithFlags(&s2, cudaStreamNonBlocking);
        cudaEventCreateWithFlags(&evA, cudaEventDisableTiming);
        cudaEventCreateWithFlags(&evB, cudaEventDisableTiming);
    }

    // fork: GEMM (depends only on x, W) runs concurrently with the CSR build
    cudaEventRecord(evA, 0);
    cudaStreamWaitEvent(s2, evA, 0);
    k_gemm<<<NNODES / 32, 256, 0, s2>>>(x, wgt);
    cudaEventRecord(evB, s2);

    // bucket build on the main (capture) stream
    void* cnt_ptr = nullptr; cudaGetSymbolAddress(&cnt_ptr, g_cnt4);
    void* deg_ptr = nullptr; cudaGetSymbolAddress(&deg_ptr, g_deg4);
    cudaMemsetAsync(cnt_ptr, 0, NNODES * NREP * sizeof(int), 0);
    cudaMemsetAsync(deg_ptr, 0, NNODES * NREP * sizeof(float), 0);
    k_scatter<<<NEDGES / 256, 256>>>(rows, cols, ew);
    k_dinv<<<NNODES / 256, 256>>>();

    // join, then SpMM
    cudaStreamWaitEvent(0, evB, 0);
    k_spmm<<<NNODES / 8, 256>>>(bias, out);
}

// round 7
// speedup vs baseline: 1.5227x; 1.0800x over previous
#include <cuda_runtime.h>
#include <cuda_bf16.h>

#define NNODES 8192
#define NEDGES 262144
#define NFEAT  128
#define NREP   4
#define CAP    48        // max edges per (row, rep) sub-bucket

// ---------------- device scratch (no allocation allowed) ----------------
__device__ __align__(16) float g_support[NNODES * NFEAT];        // x @ W (4 MB)
__device__ __align__(16) float g_dinv[NNODES];
__device__ __align__(16) int   g_cnt4[NNODES * NREP];            // bucket cursors
__device__ __align__(16) int2  g_bucket[NNODES * NREP * CAP];    // {col, w} (12.6 MB)

// ---------------- K1: single-pass bucketed scatter ----------------
__global__ void k_scatter(const int* __restrict__ rows,
                          const int* __restrict__ cols,
                          const float* __restrict__ ew) {
    int e = blockIdx.x * blockDim.x + threadIdx.x;
    int r = rows[e];
    int rep = e & 3;
    int slot = r * 4 + rep;
    int pos = atomicAdd(&g_cnt4[slot], 1);
    g_bucket[slot * CAP + pos] = make_int2(cols[e], __float_as_int(ew[e]));
}

// ---------------- K2: deg from buckets + dinv (warp per row) ----------------
__global__ __launch_bounds__(256) void k_dinv() {
    int warp = (blockIdx.x * blockDim.x + threadIdx.x) >> 5;
    int lane = threadIdx.x & 31;
    if (warp >= NNODES) return;
    int row = warp;
    int4 cnt = *(const int4*)&g_cnt4[row * 4];
    int rep = lane >> 3;                 // 8 lanes per rep segment
    int l   = lane & 7;
    int n = (rep == 0) ? cnt.x : (rep == 1) ? cnt.y : (rep == 2) ? cnt.z : cnt.w;
    const int2* bk = &g_bucket[(row * 4 + rep) * CAP];
    float sum = 0.0f;
    for (int i = l; i < n; i += 8) sum += __int_as_float(bk[i].y);
#pragma unroll
    for (int off = 16; off; off >>= 1)
        sum += __shfl_xor_sync(0xffffffffu, sum, off);
    if (lane == 0) g_dinv[row] = rsqrtf(1.0f + sum + 1e-10f);
}

// ---------------- packed f32x2 helpers ----------------
__device__ __forceinline__ unsigned long long pack2(float lo, float hi) {
    unsigned long long r;
    asm("mov.b64 %0, {%1, %2};" : "=l"(r) : "f"(lo), "f"(hi));
    return r;
}
__device__ __forceinline__ void fma2(unsigned long long& d,
                                     unsigned long long a,
                                     unsigned long long b) {
    asm("fma.rn.f32x2 %0, %1, %2, %0;" : "+l"(d) : "l"(a), "l"(b));
}
__device__ __forceinline__ float2 unpack2(unsigned long long p) {
    float lo, hi;
    asm("mov.b64 {%0, %1}, %2;" : "=f"(lo), "=f"(hi) : "l"(p));
    return make_float2(lo, hi);
}

// ---------------- K3: support = x @ W  (8192x128x128 fp32, f32x2 FMA) -------
__global__ __launch_bounds__(256) void k_gemm(const float* __restrict__ x,
                                              const float* __restrict__ w) {
    __shared__ __align__(16) float s_x[32][32];
    __shared__ __align__(16) float s_w[32][128];
    int tid = threadIdx.x;
    int row_base = blockIdx.x * 32;
    int c0 = (tid & 31) * 4;
    int r0 = (tid >> 5) * 4;

    unsigned long long acc2[4][2];
#pragma unroll
    for (int i = 0; i < 4; i++) { acc2[i][0] = 0ull; acc2[i][1] = 0ull; }

    for (int kk = 0; kk < 128; kk += 32) {
#pragma unroll
        for (int q = 0; q < 4; q++) {
            int e = tid + 256 * q;
            int r = e >> 5, kl = e & 31;
            s_x[r][kl] = x[(row_base + r) * 128 + kk + kl];
        }
#pragma unroll
        for (int q = 0; q < 4; q++) {
            int p = tid + 256 * q;
            int kr = p >> 5, cc = (p & 31) * 4;
            *(float4*)&s_w[kr][cc] = *(const float4*)&w[(kk + kr) * 128 + cc];
        }
        __syncthreads();
#pragma unroll
        for (int k = 0; k < 32; k++) {
            float4 bv = *(float4*)&s_w[k][c0];
            unsigned long long b01 = pack2(bv.x, bv.y);
            unsigned long long b23 = pack2(bv.z, bv.w);
#pragma unroll
            for (int i = 0; i < 4; i++) {
                float av = s_x[r0 + i][k];
                unsigned long long aa = pack2(av, av);
                fma2(acc2[i][0], aa, b01);
                fma2(acc2[i][1], aa, b23);
            }
        }
        __syncthreads();
    }
#pragma unroll
    for (int i = 0; i < 4; i++) {
        float2 lo = unpack2(acc2[i][0]);
        float2 hi = unpack2(acc2[i][1]);
        *(float4*)&g_support[(row_base + r0 + i) * 128 + c0] =
            make_float4(lo.x, lo.y, hi.x, hi.y);
    }
}

// ---------------- K4: SpMM, cross-rep interleaved (warp per row) ------------
// 4 independent load chains per iteration; rep guards are warp-uniform.
__global__ __launch_bounds__(256) void k_spmm(const float* __restrict__ bias,
                                              float* __restrict__ out) {
    int warp = (blockIdx.x * blockDim.x + threadIdx.x) >> 5;
    int lane = threadIdx.x & 31;
    if (warp >= NNODES) return;
    int row = warp;
    float di = g_dinv[row];
    int4 cnt = *(const int4*)&g_cnt4[row * 4];
    int n0 = cnt.x, n1 = cnt.y, n2 = cnt.z, n3 = cnt.w;
    int nmax = max(max(n0, n1), max(n2, n3));

    const int2* b0 = &g_bucket[(row * 4 + 0) * CAP];
    const int2* b1 = &g_bucket[(row * 4 + 1) * CAP];
    const int2* b2 = &g_bucket[(row * 4 + 2) * CAP];
    const int2* b3 = &g_bucket[(row * 4 + 3) * CAP];

    float ax = 0.f, ay = 0.f, az = 0.f, aw = 0.f;
    int foff = lane * 4;

    for (int i = 0; i < nmax; i++) {
        if (i < n0) {
            int2 e = b0[i];
            float v = __int_as_float(e.y) * g_dinv[e.x];
            float4 s = *(const float4*)&g_support[e.x * 128 + foff];
            ax += v * s.x; ay += v * s.y; az += v * s.z; aw += v * s.w;
        }
        if (i < n1) {
            int2 e = b1[i];
            float v = __int_as_float(e.y) * g_dinv[e.x];
            float4 s = *(const float4*)&g_support[e.x * 128 + foff];
            ax += v * s.x; ay += v * s.y; az += v * s.z; aw += v * s.w;
        }
        if (i < n2) {
            int2 e = b2[i];
            float v = __int_as_float(e.y) * g_dinv[e.x];
            float4 s = *(const float4*)&g_support[e.x * 128 + foff];
            ax += v * s.x; ay += v * s.y; az += v * s.z; aw += v * s.w;
        }
        if (i < n3) {
            int2 e = b3[i];
            float v = __int_as_float(e.y) * g_dinv[e.x];
            float4 s = *(const float4*)&g_support[e.x * 128 + foff];
            ax += v * s.x; ay += v * s.y; az += v * s.z; aw += v * s.w;
        }
    }
    // self-loop: dinv[row]^2 * support[row]
    {
        float4 sv = *(const float4*)&g_support[row * 128 + foff];
        ax += di * sv.x; ay += di * sv.y; az += di * sv.z; aw += di * sv.w;
    }
    float4 b = *(const float4*)&bias[foff];
    float4 o;
    o.x = di * ax + b.x;
    o.y = di * ay + b.y;
    o.z = di * az + b.z;
    o.w = di * aw + b.w;
    *(float4*)&out[row * 128 + foff] = o;
}

// ---------------- launch ----------------
extern "C" void kernel_launch(void* const* d_in, const int* in_sizes, int n_in,
                              void* d_out, int out_size) {
    const float* x    = (const float*)d_in[0];
    const int*   adj  = (const int*)d_in[1];     // int32 [2, E]
    const float* ew   = (const float*)d_in[2];
    const float* wgt  = (const float*)d_in[3];
    const float* bias = (const float*)d_in[4];
    float* out = (float*)d_out;

    const int* rows = adj;
    const int* cols = adj + NEDGES;

    // one-time side resources (host-side only; no device allocation)
    static cudaStream_t s2 = nullptr;
    static cudaEvent_t evA = nullptr, evB = nullptr;
    if (s2 == nullptr) {
        cudaStreamCreateWithFlags(&s2, cudaStreamNonBlocking);
        cudaEventCreateWithFlags(&evA, cudaEventDisableTiming);
        cudaEventCreateWithFlags(&evB, cudaEventDisableTiming);
    }

    // fork: GEMM (depends only on x, W) runs concurrently with the bucket build
    cudaEventRecord(evA, 0);
    cudaStreamWaitEvent(s2, evA, 0);
    k_gemm<<<NNODES / 32, 256, 0, s2>>>(x, wgt);
    cudaEventRecord(evB, s2);

    // bucket build on the main (capture) stream
    void* cnt_ptr = nullptr; cudaGetSymbolAddress(&cnt_ptr, g_cnt4);
    cudaMemsetAsync(cnt_ptr, 0, NNODES * NREP * sizeof(int), 0);
    k_scatter<<<NEDGES / 256, 256>>>(rows, cols, ew);
    k_dinv<<<NNODES / 8, 256>>>();

    // join, then SpMM
    cudaStreamWaitEvent(0, evB, 0);
    k_spmm<<<NNODES / 8, 256>>>(bias, out);
}